// round 1
// baseline (speedup 1.0000x reference)
#include <cuda_runtime.h>
#include <math.h>

#define BPAR   4
#define NSEQ   4096
#define DMODEL 1024
#define NH     16
#define DH     64
#define WIN    256
#define MTOK   (BPAR * NSEQ)     /* 16384 */
#define QKVC   (3 * NH * DH)     /* 3072  */

// Scratch (allocation-free rule: __device__ globals)
__device__ float g_qkv[(size_t)MTOK * QKVC];   // ~201 MB
__device__ float g_att[(size_t)MTOK * DMODEL]; // ~67 MB

// ---------------------------------------------------------------------------
// C[M,N] = A[M,K] @ B[K,N], row-major. M,N % 128 == 0, K % 8 == 0.
// 128x128 tile, BK=8, 256 threads, 8x8 microtile.
// ---------------------------------------------------------------------------
__global__ __launch_bounds__(256) void gemm_tiled(
    const float* __restrict__ A, const float* __restrict__ B,
    float* __restrict__ C, int M, int N, int K)
{
    __shared__ float As[8][128];
    __shared__ float Bs[8][128];

    const int tid = threadIdx.x;
    const int tx  = tid & 15;   // output col group
    const int ty  = tid >> 4;   // output row group
    const int m0  = blockIdx.y * 128;
    const int n0  = blockIdx.x * 128;

    // A tile load mapping: one float4 per thread
    const int arow = tid >> 1;          // 0..127
    const int akk  = (tid & 1) * 4;     // 0 or 4
    // B tile load mapping: one float4 per thread
    const int bk   = tid >> 5;          // 0..7
    const int bcol = (tid & 31) * 4;    // 0..124

    float acc[8][8];
    #pragma unroll
    for (int i = 0; i < 8; i++)
        #pragma unroll
        for (int j = 0; j < 8; j++) acc[i][j] = 0.f;

    for (int k0 = 0; k0 < K; k0 += 8) {
        float4 av = *reinterpret_cast<const float4*>(
            &A[(size_t)(m0 + arow) * K + k0 + akk]);
        float4 bv = *reinterpret_cast<const float4*>(
            &B[(size_t)(k0 + bk) * N + n0 + bcol]);
        As[akk + 0][arow] = av.x;
        As[akk + 1][arow] = av.y;
        As[akk + 2][arow] = av.z;
        As[akk + 3][arow] = av.w;
        *reinterpret_cast<float4*>(&Bs[bk][bcol]) = bv;
        __syncthreads();

        #pragma unroll
        for (int kk = 0; kk < 8; kk++) {
            float a[8], b[8];
            *(float4*)&a[0] = *(float4*)&As[kk][ty * 8];
            *(float4*)&a[4] = *(float4*)&As[kk][ty * 8 + 4];
            *(float4*)&b[0] = *(float4*)&Bs[kk][tx * 8];
            *(float4*)&b[4] = *(float4*)&Bs[kk][tx * 8 + 4];
            #pragma unroll
            for (int i = 0; i < 8; i++)
                #pragma unroll
                for (int j = 0; j < 8; j++)
                    acc[i][j] = fmaf(a[i], b[j], acc[i][j]);
        }
        __syncthreads();
    }

    #pragma unroll
    for (int i = 0; i < 8; i++) {
        float* crow = &C[(size_t)(m0 + ty * 8 + i) * N + n0 + tx * 8];
        *reinterpret_cast<float4*>(crow)     =
            make_float4(acc[i][0], acc[i][1], acc[i][2], acc[i][3]);
        *reinterpret_cast<float4*>(crow + 4) =
            make_float4(acc[i][4], acc[i][5], acc[i][6], acc[i][7]);
    }
}

// ---------------------------------------------------------------------------
// Sliding-window attention. grid = (nb=16, B*H=64), block = 256 (thread = query).
// Each query block sees keys jj in [0, 2W) where abs key = (blk-1)*W + jj.
// valid: jj in [ii+1, ii+W] (and abs key >= 0).
// Online softmax with 8-key deferred rescale; K/V streamed in 64-key chunks.
// ---------------------------------------------------------------------------
__global__ __launch_bounds__(256) void swa_kernel(
    const float* __restrict__ qkv, float* __restrict__ attout)
{
    const int blk  = blockIdx.x;       // query block 0..15
    const int bh   = blockIdx.y;       // b*NH + h
    const int b    = bh >> 4;
    const int h    = bh & 15;
    const int tid  = threadIdx.x;      // query ii
    const int warp = tid >> 5;

    __shared__ float ks[64][64];
    __shared__ float vs[64][64];

    // q into registers, pre-scaled by DH^-1/2
    float q[64];
    {
        const float* qp = &qkv[(size_t)(b * NSEQ + blk * WIN + tid) * QKVC + h * DH];
        #pragma unroll
        for (int d4 = 0; d4 < 16; d4++) {
            float4 v = *reinterpret_cast<const float4*>(qp + d4 * 4);
            q[d4 * 4 + 0] = v.x * 0.125f;
            q[d4 * 4 + 1] = v.y * 0.125f;
            q[d4 * 4 + 2] = v.z * 0.125f;
            q[d4 * 4 + 3] = v.w * 0.125f;
        }
    }

    float acc[64];
    #pragma unroll
    for (int d = 0; d < 64; d++) acc[d] = 0.f;
    float m = -1e30f, l = 0.f;

    // per-warp valid jj range
    const int wq0 = warp * 32;
    int wlo = wq0 + 1;
    if (blk == 0 && wlo < WIN) wlo = WIN;   // pad block fully masked
    const int whi = wq0 + 31 + WIN;          // inclusive

    // chunk-load mapping: thread -> (key row, 16-float segment)
    const int ldj  = tid >> 2;
    const int ldsg = (tid & 3) * 16;

    for (int c = 0; c < 8; c++) {
        const int j0 = c * 64;
        // cooperative K/V chunk load
        {
            const int jj   = j0 + ldj;
            const int kabs = (blk - 1) * WIN + jj;
            if (kabs >= 0) {
                const float* kp = &qkv[(size_t)(b * NSEQ + kabs) * QKVC + DMODEL + h * DH + ldsg];
                const float* vp = kp + DMODEL;
                #pragma unroll
                for (int i = 0; i < 4; i++) {
                    *reinterpret_cast<float4*>(&ks[ldj][ldsg + i * 4]) =
                        *reinterpret_cast<const float4*>(kp + i * 4);
                    *reinterpret_cast<float4*>(&vs[ldj][ldsg + i * 4]) =
                        *reinterpret_cast<const float4*>(vp + i * 4);
                }
            } else {
                #pragma unroll
                for (int i = 0; i < 4; i++) {
                    *reinterpret_cast<float4*>(&ks[ldj][ldsg + i * 4]) = make_float4(0, 0, 0, 0);
                    *reinterpret_cast<float4*>(&vs[ldj][ldsg + i * 4]) = make_float4(0, 0, 0, 0);
                }
            }
        }
        __syncthreads();

        const int jb = max(j0, wlo);
        const int je = min(j0 + 64, whi + 1);
        for (int j = jb; j < je; j += 8) {
            float s[8];
            int   row[8];
            #pragma unroll
            for (int u = 0; u < 8; u++) {
                const int jj = j + u;
                row[u] = (jj - j0) & 63;   // clamp (out-of-range lanes are masked)
                float p0 = 0.f, p1 = 0.f, p2 = 0.f, p3 = 0.f;
                const float* kr = ks[row[u]];
                #pragma unroll
                for (int d4 = 0; d4 < 16; d4++) {
                    float4 kv = *reinterpret_cast<const float4*>(kr + d4 * 4);
                    p0 = fmaf(q[d4 * 4 + 0], kv.x, p0);
                    p1 = fmaf(q[d4 * 4 + 1], kv.y, p1);
                    p2 = fmaf(q[d4 * 4 + 2], kv.z, p2);
                    p3 = fmaf(q[d4 * 4 + 3], kv.w, p3);
                }
                const bool valid = (jj < je) && (jj >= tid + 1) && (jj <= tid + WIN);
                s[u] = valid ? ((p0 + p1) + (p2 + p3)) : -1e35f;
            }

            float cmax = s[0];
            #pragma unroll
            for (int u = 1; u < 8; u++) cmax = fmaxf(cmax, s[u]);
            const float mn   = fmaxf(m, cmax);
            const float corr = __expf(m - mn);
            m = mn;

            float p[8], ps = 0.f;
            #pragma unroll
            for (int u = 0; u < 8; u++) { p[u] = __expf(s[u] - mn); ps += p[u]; }
            l = l * corr + ps;

            #pragma unroll
            for (int d = 0; d < 64; d++) acc[d] *= corr;
            #pragma unroll
            for (int u = 0; u < 8; u++) {
                const float* vr = vs[row[u]];
                const float  pu = p[u];
                #pragma unroll
                for (int d4 = 0; d4 < 16; d4++) {
                    float4 vv = *reinterpret_cast<const float4*>(vr + d4 * 4);
                    acc[d4 * 4 + 0] = fmaf(pu, vv.x, acc[d4 * 4 + 0]);
                    acc[d4 * 4 + 1] = fmaf(pu, vv.y, acc[d4 * 4 + 1]);
                    acc[d4 * 4 + 2] = fmaf(pu, vv.z, acc[d4 * 4 + 2]);
                    acc[d4 * 4 + 3] = fmaf(pu, vv.w, acc[d4 * 4 + 3]);
                }
            }
        }
        __syncthreads();
    }

    const float inv = 1.f / l;
    float* op = &attout[(size_t)(b * NSEQ + blk * WIN + tid) * DMODEL + h * DH];
    #pragma unroll
    for (int d4 = 0; d4 < 16; d4++) {
        *reinterpret_cast<float4*>(op + d4 * 4) =
            make_float4(acc[d4 * 4 + 0] * inv, acc[d4 * 4 + 1] * inv,
                        acc[d4 * 4 + 2] * inv, acc[d4 * 4 + 3] * inv);
    }
}

// ---------------------------------------------------------------------------
extern "C" void kernel_launch(void* const* d_in, const int* in_sizes, int n_in,
                              void* d_out, int out_size)
{
    const float* x     = (const float*)d_in[0];   // [4,4096,1024]
    const float* w_qkv = (const float*)d_in[1];   // [1024,3072]
    const float* w_out = (const float*)d_in[2];   // [1024,1024]
    float*       out   = (float*)d_out;           // [4,4096,1024]

    float *qkv, *att;
    cudaGetSymbolAddress((void**)&qkv, g_qkv);
    cudaGetSymbolAddress((void**)&att, g_att);

    dim3 tb(256);
    gemm_tiled<<<dim3(QKVC / 128, MTOK / 128), tb>>>(x, w_qkv, qkv, MTOK, QKVC, DMODEL);
    swa_kernel<<<dim3(NSEQ / WIN, BPAR * NH), tb>>>(qkv, att);
    gemm_tiled<<<dim3(DMODEL / 128, MTOK / 128), tb>>>(att, w_out, out, MTOK, DMODEL, DMODEL);
}

// round 3
// speedup vs baseline: 1.6384x; 1.6384x over previous
#include <cuda_runtime.h>
#include <cuda_bf16.h>
#include <math.h>

#define BPAR   4
#define NSEQ   4096
#define DMODEL 1024
#define NH     16
#define DH     64
#define WIN    256
#define MTOK   (BPAR * NSEQ)     /* 16384 */
#define QKVC   (3 * NH * DH)     /* 3072  */

// Scratch (allocation-free rule: __device__ globals)
__device__ float g_qkv[(size_t)MTOK * QKVC];   // ~201 MB
__device__ float g_att[(size_t)MTOK * DMODEL]; // ~67 MB

// ---------------------------------------------------------------------------
// packed f32x2 ops (PTX-only; ptxas never auto-fuses FFMA2). sm_100-family OK.
// ---------------------------------------------------------------------------
__device__ __forceinline__ unsigned long long pk2(float x, float y) {
    unsigned long long r;
    asm("mov.b64 %0,{%1,%2};" : "=l"(r) : "f"(x), "f"(y));
    return r;
}
__device__ __forceinline__ float2 up2(unsigned long long v) {
    float2 r;
    asm("mov.b64 {%0,%1},%2;" : "=f"(r.x), "=f"(r.y) : "l"(v));
    return r;
}
__device__ __forceinline__ unsigned long long f2fma(
    unsigned long long a, unsigned long long b, unsigned long long c) {
    unsigned long long d;
    asm("fma.rn.f32x2 %0,%1,%2,%3;" : "=l"(d) : "l"(a), "l"(b), "l"(c));
    return d;
}
__device__ __forceinline__ unsigned long long f2mul(
    unsigned long long a, unsigned long long b) {
    unsigned long long d;
    asm("mul.rn.f32x2 %0,%1,%2;" : "=l"(d) : "l"(a), "l"(b));
    return d;
}
__device__ __forceinline__ unsigned long long f2add(
    unsigned long long a, unsigned long long b) {
    unsigned long long d;
    asm("add.rn.f32x2 %0,%1,%2;" : "=l"(d) : "l"(a), "l"(b));
    return d;
}

// split fp32 pair -> bf16x2 hi word + bf16x2 lo word (a = hi + lo exactly to ~2^-17)
__device__ __forceinline__ void split2(float x, float y, unsigned& h, unsigned& l) {
    unsigned xb = __float_as_uint(x) & 0xFFFF0000u;
    unsigned yb = __float_as_uint(y) & 0xFFFF0000u;
    h = __byte_perm(xb, yb, 0x7632);
    float rx = x - __uint_as_float(xb);
    float ry = y - __uint_as_float(yb);
    __nv_bfloat162 t = __floats2bfloat162_rn(rx, ry);
    l = *reinterpret_cast<unsigned*>(&t);
}

__device__ __forceinline__ void mma16816(
    float& c0, float& c1, float& c2, float& c3,
    unsigned a0, unsigned a1, unsigned a2, unsigned a3,
    unsigned b0, unsigned b1) {
    asm volatile(
        "mma.sync.aligned.m16n8k16.row.col.f32.bf16.bf16.f32 "
        "{%0,%1,%2,%3},{%4,%5,%6,%7},{%8,%9},{%0,%1,%2,%3};"
        : "+f"(c0), "+f"(c1), "+f"(c2), "+f"(c3)
        : "r"(a0), "r"(a1), "r"(a2), "r"(a3), "r"(b0), "r"(b1));
}

// ---------------------------------------------------------------------------
// split-bf16 HMMA GEMM: C[M,N] = A[M,K] @ B[K,N], fp32 in/out.
// 128x128 CTA tile, 256 thr (8 warps 2x4 -> 64x32 warp tile), K chunks of 32.
// Both operands stored K-contiguous in smem (B transposed at convert time);
// row stride = 20 words (80B) -> conflict-free fragment LDS.32.
// K must be a multiple of 32 (K=1024 here).
// ---------------------------------------------------------------------------
#define ROWW 20
__global__ __launch_bounds__(256, 2) void gemm_mma(
    const float* __restrict__ A, const float* __restrict__ B,
    float* __restrict__ C, int M, int N, int K)
{
    __shared__ unsigned sAh[128 * ROWW], sAl[128 * ROWW];
    __shared__ unsigned sBh[128 * ROWW], sBl[128 * ROWW];

    const int tid = threadIdx.x;
    const int wid = tid >> 5, lid = tid & 31;
    const int g = lid >> 2, t = lid & 3;
    const int wm = (wid >> 2) * 64;   // warp m offset (0 / 64)
    const int wn = (wid & 3) * 32;    // warp n offset
    const int m0 = blockIdx.y * 128, n0 = blockIdx.x * 128;

    // convert-pass mapping: 2 threads per row, each 16 values (= half*16 k-off)
    const int cr = tid >> 1, ch = (tid & 1) * 16;

    float acc[4][4][4];
    #pragma unroll
    for (int i = 0; i < 4; i++)
        #pragma unroll
        for (int j = 0; j < 4; j++)
            #pragma unroll
            for (int e = 0; e < 4; e++) acc[i][j][e] = 0.f;

    for (int k0 = 0; k0 < K; k0 += 32) {
        // ---- A convert: row cr, k [k0+ch, k0+ch+16) ----
        {
            const float* ar = A + (size_t)(m0 + cr) * K + k0 + ch;
            uint4 h0, l0, h1, l1;
            float4 f;
            f = *reinterpret_cast<const float4*>(ar + 0);
            split2(f.x, f.y, h0.x, l0.x); split2(f.z, f.w, h0.y, l0.y);
            f = *reinterpret_cast<const float4*>(ar + 4);
            split2(f.x, f.y, h0.z, l0.z); split2(f.z, f.w, h0.w, l0.w);
            f = *reinterpret_cast<const float4*>(ar + 8);
            split2(f.x, f.y, h1.x, l1.x); split2(f.z, f.w, h1.y, l1.y);
            f = *reinterpret_cast<const float4*>(ar + 12);
            split2(f.x, f.y, h1.z, l1.z); split2(f.z, f.w, h1.w, l1.w);
            const int o = cr * ROWW + (ch >> 1);   // word offset (2 bf16/word)
            *reinterpret_cast<uint4*>(&sAh[o])     = h0;
            *reinterpret_cast<uint4*>(&sAh[o + 4]) = h1;
            *reinterpret_cast<uint4*>(&sAl[o])     = l0;
            *reinterpret_cast<uint4*>(&sAl[o + 4]) = l1;
        }
        // ---- B convert (transpose): smem row = output col, k-contiguous ----
        {
            const float* bp = B + (size_t)(k0 + ch) * N + n0 + cr;
            float v[16];
            #pragma unroll
            for (int kk = 0; kk < 16; kk++) v[kk] = bp[(size_t)kk * N];
            uint4 h0, l0, h1, l1;
            split2(v[0],  v[1],  h0.x, l0.x); split2(v[2],  v[3],  h0.y, l0.y);
            split2(v[4],  v[5],  h0.z, l0.z); split2(v[6],  v[7],  h0.w, l0.w);
            split2(v[8],  v[9],  h1.x, l1.x); split2(v[10], v[11], h1.y, l1.y);
            split2(v[12], v[13], h1.z, l1.z); split2(v[14], v[15], h1.w, l1.w);
            const int o = cr * ROWW + (ch >> 1);
            *reinterpret_cast<uint4*>(&sBh[o])     = h0;
            *reinterpret_cast<uint4*>(&sBh[o + 4]) = h1;
            *reinterpret_cast<uint4*>(&sBl[o])     = l0;
            *reinterpret_cast<uint4*>(&sBl[o + 4]) = l1;
        }
        __syncthreads();

        #pragma unroll
        for (int s = 0; s < 2; s++) {
            const int w = s * 8 + t;
            unsigned ah[4][4], al[4][4];
            #pragma unroll
            for (int tm = 0; tm < 4; tm++) {
                const int r0 = (wm + tm * 16 + g) * ROWW;
                const int r1 = r0 + 8 * ROWW;
                ah[tm][0] = sAh[r0 + w]; ah[tm][1] = sAh[r1 + w];
                ah[tm][2] = sAh[r0 + w + 4]; ah[tm][3] = sAh[r1 + w + 4];
                al[tm][0] = sAl[r0 + w]; al[tm][1] = sAl[r1 + w];
                al[tm][2] = sAl[r0 + w + 4]; al[tm][3] = sAl[r1 + w + 4];
            }
            #pragma unroll
            for (int tn = 0; tn < 4; tn++) {
                const int nr = (wn + tn * 8 + g) * ROWW;
                const unsigned bh0 = sBh[nr + w], bh1 = sBh[nr + w + 4];
                const unsigned bl0 = sBl[nr + w], bl1 = sBl[nr + w + 4];
                #pragma unroll
                for (int tm = 0; tm < 4; tm++) {
                    float* c = acc[tm][tn];
                    mma16816(c[0], c[1], c[2], c[3],
                             ah[tm][0], ah[tm][1], ah[tm][2], ah[tm][3], bh0, bh1);
                    mma16816(c[0], c[1], c[2], c[3],
                             ah[tm][0], ah[tm][1], ah[tm][2], ah[tm][3], bl0, bl1);
                    mma16816(c[0], c[1], c[2], c[3],
                             al[tm][0], al[tm][1], al[tm][2], al[tm][3], bh0, bh1);
                }
            }
        }
        __syncthreads();
    }

    // epilogue
    #pragma unroll
    for (int tm = 0; tm < 4; tm++) {
        #pragma unroll
        for (int tn = 0; tn < 4; tn++) {
            float* c = acc[tm][tn];
            float* p0 = C + (size_t)(m0 + wm + tm * 16 + g) * N + n0 + wn + tn * 8 + 2 * t;
            *reinterpret_cast<float2*>(p0)               = make_float2(c[0], c[1]);
            *reinterpret_cast<float2*>(p0 + (size_t)8 * N) = make_float2(c[2], c[3]);
        }
    }
}

// ---------------------------------------------------------------------------
// Sliding-window attention, f32x2-packed math. grid=(16, 64), block=256.
// ---------------------------------------------------------------------------
__global__ __launch_bounds__(256) void swa_kernel(
    const float* __restrict__ qkv, float* __restrict__ attout)
{
    const int blk  = blockIdx.x;
    const int bh   = blockIdx.y;
    const int b    = bh >> 4;
    const int h    = bh & 15;
    const int tid  = threadIdx.x;
    const int warp = tid >> 5;

    __shared__ float ks[64][64];
    __shared__ float vs[64][64];

    unsigned long long qp[32];
    {
        const float* qpail = &qkv[(size_t)(b * NSEQ + blk * WIN + tid) * QKVC + h * DH];
        #pragma unroll
        for (int d4 = 0; d4 < 16; d4++) {
            float4 v = *reinterpret_cast<const float4*>(qpail + d4 * 4);
            qp[d4 * 2 + 0] = pk2(v.x * 0.125f, v.y * 0.125f);
            qp[d4 * 2 + 1] = pk2(v.z * 0.125f, v.w * 0.125f);
        }
    }

    unsigned long long accp[32];
    #pragma unroll
    for (int i = 0; i < 32; i++) accp[i] = 0ull;
    float m = -1e30f, l = 0.f;

    const int wq0 = warp * 32;
    int wlo = wq0 + 1;
    if (blk == 0 && wlo < WIN) wlo = WIN;
    const int whi = wq0 + 31 + WIN;

    const int ldj  = tid >> 2;
    const int ldsg = (tid & 3) * 16;

    for (int c = 0; c < 8; c++) {
        const int j0 = c * 64;
        {
            const int jj   = j0 + ldj;
            const int kabs = (blk - 1) * WIN + jj;
            if (kabs >= 0) {
                const float* kp = &qkv[(size_t)(b * NSEQ + kabs) * QKVC + DMODEL + h * DH + ldsg];
                const float* vp = kp + DMODEL;
                #pragma unroll
                for (int i = 0; i < 4; i++) {
                    *reinterpret_cast<float4*>(&ks[ldj][ldsg + i * 4]) =
                        *reinterpret_cast<const float4*>(kp + i * 4);
                    *reinterpret_cast<float4*>(&vs[ldj][ldsg + i * 4]) =
                        *reinterpret_cast<const float4*>(vp + i * 4);
                }
            } else {
                #pragma unroll
                for (int i = 0; i < 4; i++) {
                    *reinterpret_cast<float4*>(&ks[ldj][ldsg + i * 4]) = make_float4(0, 0, 0, 0);
                    *reinterpret_cast<float4*>(&vs[ldj][ldsg + i * 4]) = make_float4(0, 0, 0, 0);
                }
            }
        }
        __syncthreads();

        const int jb = max(j0, wlo);
        const int je = min(j0 + 64, whi + 1);
        for (int j = jb; j < je; j += 8) {
            float s[8];
            int   row[8];
            #pragma unroll
            for (int u = 0; u < 8; u++) {
                const int jj = j + u;
                row[u] = (jj - j0) & 63;
                const ulonglong2* kr2 = reinterpret_cast<const ulonglong2*>(ks[row[u]]);
                unsigned long long s0 = 0ull, s1 = 0ull;
                #pragma unroll
                for (int i = 0; i < 16; i++) {
                    ulonglong2 kv = kr2[i];
                    s0 = f2fma(qp[2 * i + 0], kv.x, s0);
                    s1 = f2fma(qp[2 * i + 1], kv.y, s1);
                }
                float2 f = up2(f2add(s0, s1));
                const bool valid = (jj < je) && (jj >= tid + 1) && (jj <= tid + WIN);
                s[u] = valid ? (f.x + f.y) : -1e35f;
            }

            float cmax = s[0];
            #pragma unroll
            for (int u = 1; u < 8; u++) cmax = fmaxf(cmax, s[u]);
            const float mn   = fmaxf(m, cmax);
            const float corr = __expf(m - mn);
            m = mn;

            float p[8], psum = 0.f;
            #pragma unroll
            for (int u = 0; u < 8; u++) { p[u] = __expf(s[u] - mn); psum += p[u]; }
            l = l * corr + psum;

            const unsigned long long cp = pk2(corr, corr);
            #pragma unroll
            for (int i = 0; i < 32; i++) accp[i] = f2mul(accp[i], cp);
            #pragma unroll
            for (int u = 0; u < 8; u++) {
                const ulonglong2* vr2 = reinterpret_cast<const ulonglong2*>(vs[row[u]]);
                const unsigned long long pp = pk2(p[u], p[u]);
                #pragma unroll
                for (int i = 0; i < 16; i++) {
                    ulonglong2 vv = vr2[i];
                    accp[2 * i + 0] = f2fma(pp, vv.x, accp[2 * i + 0]);
                    accp[2 * i + 1] = f2fma(pp, vv.y, accp[2 * i + 1]);
                }
            }
        }
        __syncthreads();
    }

    const float inv = 1.f / l;
    float* op = &attout[(size_t)(b * NSEQ + blk * WIN + tid) * DMODEL + h * DH];
    #pragma unroll
    for (int i = 0; i < 16; i++) {
        float2 a = up2(accp[2 * i + 0]);
        float2 bq = up2(accp[2 * i + 1]);
        *reinterpret_cast<float4*>(op + i * 4) =
            make_float4(a.x * inv, a.y * inv, bq.x * inv, bq.y * inv);
    }
}

// ---------------------------------------------------------------------------
extern "C" void kernel_launch(void* const* d_in, const int* in_sizes, int n_in,
                              void* d_out, int out_size)
{
    const float* x     = (const float*)d_in[0];   // [4,4096,1024]
    const float* w_qkv = (const float*)d_in[1];   // [1024,3072]
    const float* w_out = (const float*)d_in[2];   // [1024,1024]
    float*       out   = (float*)d_out;           // [4,4096,1024]

    float *qkv, *att;
    cudaGetSymbolAddress((void**)&qkv, g_qkv);
    cudaGetSymbolAddress((void**)&att, g_att);

    gemm_mma<<<dim3(QKVC / 128, MTOK / 128), 256>>>(x, w_qkv, qkv, MTOK, QKVC, DMODEL);
    swa_kernel<<<dim3(NSEQ / WIN, BPAR * NH), 256>>>(qkv, att);
    gemm_mma<<<dim3(DMODEL / 128, MTOK / 128), 256>>>(att, w_out, out, MTOK, DMODEL, DMODEL);
}

// round 4
// speedup vs baseline: 2.0040x; 1.2232x over previous
#include <cuda_runtime.h>
#include <cuda_bf16.h>
#include <math.h>

#define BPAR   4
#define NSEQ   4096
#define DMODEL 1024
#define NH     16
#define DH     64
#define WIN    256
#define MTOK   (BPAR * NSEQ)     /* 16384 */
#define QKVC   (3 * NH * DH)     /* 3072  */

// Scratch (allocation-free rule: __device__ globals)
__device__ float         g_qkv[(size_t)MTOK * QKVC];            // ~201 MB fp32
__device__ __nv_bfloat16 g_xh[(size_t)MTOK * DMODEL];           // x split hi
__device__ __nv_bfloat16 g_xl[(size_t)MTOK * DMODEL];           // x split lo
__device__ __nv_bfloat16 g_ah[(size_t)MTOK * DMODEL];           // attn out hi
__device__ __nv_bfloat16 g_al[(size_t)MTOK * DMODEL];           // attn out lo
__device__ __nv_bfloat16 g_wqh[(size_t)QKVC * DMODEL];          // w_qkv^T hi [N][K]
__device__ __nv_bfloat16 g_wql[(size_t)QKVC * DMODEL];
__device__ __nv_bfloat16 g_woh[(size_t)DMODEL * DMODEL];        // w_out^T hi [N][K]
__device__ __nv_bfloat16 g_wol[(size_t)DMODEL * DMODEL];

// ---------------------------------------------------------------------------
// helpers
// ---------------------------------------------------------------------------
__device__ __forceinline__ unsigned smem_u32(const void* p) {
    unsigned a;
    asm("{ .reg .u64 t; cvta.to.shared.u64 t, %1; cvt.u32.u64 %0, t; }"
        : "=r"(a) : "l"(p));
    return a;
}
__device__ __forceinline__ unsigned long long pk2(float x, float y) {
    unsigned long long r;
    asm("mov.b64 %0,{%1,%2};" : "=l"(r) : "f"(x), "f"(y));
    return r;
}
__device__ __forceinline__ float2 up2(unsigned long long v) {
    float2 r;
    asm("mov.b64 {%0,%1},%2;" : "=f"(r.x), "=f"(r.y) : "l"(v));
    return r;
}
__device__ __forceinline__ unsigned long long f2fma(
    unsigned long long a, unsigned long long b, unsigned long long c) {
    unsigned long long d;
    asm("fma.rn.f32x2 %0,%1,%2,%3;" : "=l"(d) : "l"(a), "l"(b), "l"(c));
    return d;
}
__device__ __forceinline__ unsigned long long f2mul(
    unsigned long long a, unsigned long long b) {
    unsigned long long d;
    asm("mul.rn.f32x2 %0,%1,%2;" : "=l"(d) : "l"(a), "l"(b));
    return d;
}
__device__ __forceinline__ unsigned long long f2add(
    unsigned long long a, unsigned long long b) {
    unsigned long long d;
    asm("add.rn.f32x2 %0,%1,%2;" : "=l"(d) : "l"(a), "l"(b));
    return d;
}

// split fp32 pair -> bf16x2 hi word (truncated) + bf16x2 lo word (rn residual)
__device__ __forceinline__ void split2(float x, float y, unsigned& h, unsigned& l) {
    unsigned xb = __float_as_uint(x) & 0xFFFF0000u;
    unsigned yb = __float_as_uint(y) & 0xFFFF0000u;
    h = __byte_perm(xb, yb, 0x7632);
    float rx = x - __uint_as_float(xb);
    float ry = y - __uint_as_float(yb);
    __nv_bfloat162 t = __floats2bfloat162_rn(rx, ry);
    l = *reinterpret_cast<unsigned*>(&t);
}

__device__ __forceinline__ void mma16816(
    float& c0, float& c1, float& c2, float& c3,
    unsigned a0, unsigned a1, unsigned a2, unsigned a3,
    unsigned b0, unsigned b1) {
    asm volatile(
        "mma.sync.aligned.m16n8k16.row.col.f32.bf16.bf16.f32 "
        "{%0,%1,%2,%3},{%4,%5,%6,%7},{%8,%9},{%0,%1,%2,%3};"
        : "+f"(c0), "+f"(c1), "+f"(c2), "+f"(c3)
        : "r"(a0), "r"(a1), "r"(a2), "r"(a3), "r"(b0), "r"(b1));
}

__device__ __forceinline__ void cp16(unsigned saddr, const void* g) {
    asm volatile("cp.async.cg.shared.global [%0], [%1], 16;"
                 :: "r"(saddr), "l"(g) : "memory");
}

// ---------------------------------------------------------------------------
// prepass: elementwise fp32 -> bf16 hi/lo (8 floats per thread)
// ---------------------------------------------------------------------------
__global__ __launch_bounds__(256) void split_arr(
    const float4* __restrict__ src, uint4* __restrict__ hi,
    uint4* __restrict__ lo, int nvec8)
{
    int i = blockIdx.x * 256 + threadIdx.x;
    if (i >= nvec8) return;
    float4 f0 = src[2 * i], f1 = src[2 * i + 1];
    uint4 h, l;
    split2(f0.x, f0.y, h.x, l.x); split2(f0.z, f0.w, h.y, l.y);
    split2(f1.x, f1.y, h.z, l.z); split2(f1.z, f1.w, h.w, l.w);
    hi[i] = h; lo[i] = l;
}

// ---------------------------------------------------------------------------
// prepass: transpose+split. src [K][N] fp32 -> hi/lo [N][K] bf16.
// ---------------------------------------------------------------------------
__global__ void split_tr(const float* __restrict__ src,
                         __nv_bfloat16* __restrict__ hi,
                         __nv_bfloat16* __restrict__ lo, int K, int N)
{
    __shared__ float tile[32][33];
    const int n0 = blockIdx.x * 32, k0 = blockIdx.y * 32;
    const int tx = threadIdx.x, ty = threadIdx.y;
    #pragma unroll
    for (int j = ty; j < 32; j += 8)
        tile[j][tx] = src[(size_t)(k0 + j) * N + n0 + tx];
    __syncthreads();
    #pragma unroll
    for (int j = ty; j < 32; j += 8) {
        float v = tile[tx][j];
        unsigned vb = __float_as_uint(v) & 0xFFFF0000u;
        size_t o = (size_t)(n0 + j) * K + k0 + tx;
        unsigned short hs = (unsigned short)(vb >> 16);
        hi[o] = *reinterpret_cast<__nv_bfloat16*>(&hs);
        lo[o] = __float2bfloat16_rn(v - __uint_as_float(vb));
    }
}

// ---------------------------------------------------------------------------
// split-bf16 HMMA GEMM, pre-converted operands, double-buffered cp.async.
// A hi/lo: [M][K] bf16 row-major. B hi/lo: [N][K] bf16 (pre-transposed).
// C fp32 [M][N]. 128x128 CTA tile, 256 thr (2x4 warps -> 64x32), K chunk 32.
// smem/stage: 4 tiles x 128 rows x 80B (64B data + 16B pad) = 40960B.
// ---------------------------------------------------------------------------
#define TILE_B 10240
#define STG_B  40960
#define GSMEM  (2 * STG_B)

__device__ __forceinline__ void gload(
    unsigned sb, int st, int tid,
    const __nv_bfloat16* b0, const __nv_bfloat16* b1,
    const __nv_bfloat16* b2, const __nv_bfloat16* b3, int K, int k0)
{
    const __nv_bfloat16* base[4] = {b0, b1, b2, b3};
    const int rlo  = tid >> 2;
    const int pel  = (tid & 3) << 3;   // element offset within 32-k chunk
    const int pby  = (tid & 3) << 4;   // byte offset within row
    #pragma unroll
    for (int i = 0; i < 8; i++) {
        const int tl  = i >> 1;
        const int row = ((i & 1) << 6) + rlo;
        cp16(sb + st * STG_B + tl * TILE_B + row * 80 + pby,
             base[tl] + (size_t)row * K + k0 + pel);
    }
    asm volatile("cp.async.commit_group;" ::: "memory");
}

__global__ __launch_bounds__(256, 2) void gemm_mma(
    const __nv_bfloat16* __restrict__ Ah, const __nv_bfloat16* __restrict__ Al,
    const __nv_bfloat16* __restrict__ Bh, const __nv_bfloat16* __restrict__ Bl,
    float* __restrict__ C, int M, int N, int K)
{
    extern __shared__ char dsm[];
    const unsigned sb = smem_u32(dsm);

    const int tid = threadIdx.x;
    const int wid = tid >> 5, lid = tid & 31;
    const int g = lid >> 2, t = lid & 3;
    const int wm = (wid >> 2) * 64;
    const int wn = (wid & 3) * 32;
    const int m0 = blockIdx.y * 128, n0 = blockIdx.x * 128;

    const __nv_bfloat16* a_h = Ah + (size_t)m0 * K;
    const __nv_bfloat16* a_l = Al + (size_t)m0 * K;
    const __nv_bfloat16* b_h = Bh + (size_t)n0 * K;
    const __nv_bfloat16* b_l = Bl + (size_t)n0 * K;

    float acc[4][4][4];
    #pragma unroll
    for (int i = 0; i < 4; i++)
        #pragma unroll
        for (int j = 0; j < 4; j++)
            #pragma unroll
            for (int e = 0; e < 4; e++) acc[i][j][e] = 0.f;

    const int nk = K >> 5;
    gload(sb, 0, tid, a_h, a_l, b_h, b_l, K, 0);

    for (int kc = 0; kc < nk; kc++) {
        if (kc + 1 < nk) {
            gload(sb, (kc + 1) & 1, tid, a_h, a_l, b_h, b_l, K, (kc + 1) << 5);
            asm volatile("cp.async.wait_group 1;" ::: "memory");
        } else {
            asm volatile("cp.async.wait_group 0;" ::: "memory");
        }
        __syncthreads();

        const int st = kc & 1;
        const unsigned* pAh = reinterpret_cast<const unsigned*>(dsm + st * STG_B);
        const unsigned* pAl = pAh + 2560;
        const unsigned* pBh = pAh + 5120;
        const unsigned* pBl = pAh + 7680;

        #pragma unroll
        for (int s = 0; s < 2; s++) {
            const int w = s * 8 + t;
            unsigned ah[4][4], al[4][4];
            #pragma unroll
            for (int tm = 0; tm < 4; tm++) {
                const int r0 = (wm + tm * 16 + g) * 20;
                const int r1 = r0 + 8 * 20;
                ah[tm][0] = pAh[r0 + w];     ah[tm][1] = pAh[r1 + w];
                ah[tm][2] = pAh[r0 + w + 4]; ah[tm][3] = pAh[r1 + w + 4];
                al[tm][0] = pAl[r0 + w];     al[tm][1] = pAl[r1 + w];
                al[tm][2] = pAl[r0 + w + 4]; al[tm][3] = pAl[r1 + w + 4];
            }
            #pragma unroll
            for (int tn = 0; tn < 4; tn++) {
                const int nr = (wn + tn * 8 + g) * 20;
                const unsigned bh0 = pBh[nr + w], bh1 = pBh[nr + w + 4];
                const unsigned bl0 = pBl[nr + w], bl1 = pBl[nr + w + 4];
                #pragma unroll
                for (int tm = 0; tm < 4; tm++) {
                    float* c = acc[tm][tn];
                    mma16816(c[0], c[1], c[2], c[3],
                             ah[tm][0], ah[tm][1], ah[tm][2], ah[tm][3], bh0, bh1);
                    mma16816(c[0], c[1], c[2], c[3],
                             ah[tm][0], ah[tm][1], ah[tm][2], ah[tm][3], bl0, bl1);
                    mma16816(c[0], c[1], c[2], c[3],
                             al[tm][0], al[tm][1], al[tm][2], al[tm][3], bh0, bh1);
                }
            }
        }
        __syncthreads();
    }

    #pragma unroll
    for (int tm = 0; tm < 4; tm++) {
        #pragma unroll
        for (int tn = 0; tn < 4; tn++) {
            float* c = acc[tm][tn];
            float* p0 = C + (size_t)(m0 + wm + tm * 16 + g) * N + n0 + wn + tn * 8 + 2 * t;
            *reinterpret_cast<float2*>(p0)                 = make_float2(c[0], c[1]);
            *reinterpret_cast<float2*>(p0 + (size_t)8 * N) = make_float2(c[2], c[3]);
        }
    }
}

// ---------------------------------------------------------------------------
// Sliding-window attention, f32x2 math; emits bf16 hi/lo output directly.
// grid=(16, 64), block=256.
// ---------------------------------------------------------------------------
__global__ __launch_bounds__(256) void swa_kernel(
    const float* __restrict__ qkv,
    __nv_bfloat16* __restrict__ oh, __nv_bfloat16* __restrict__ ol)
{
    const int blk  = blockIdx.x;
    const int bh   = blockIdx.y;
    const int b    = bh >> 4;
    const int h    = bh & 15;
    const int tid  = threadIdx.x;
    const int warp = tid >> 5;

    __shared__ float ks[64][64];
    __shared__ float vs[64][64];

    unsigned long long qp[32];
    {
        const float* qpail = &qkv[(size_t)(b * NSEQ + blk * WIN + tid) * QKVC + h * DH];
        #pragma unroll
        for (int d4 = 0; d4 < 16; d4++) {
            float4 v = *reinterpret_cast<const float4*>(qpail + d4 * 4);
            qp[d4 * 2 + 0] = pk2(v.x * 0.125f, v.y * 0.125f);
            qp[d4 * 2 + 1] = pk2(v.z * 0.125f, v.w * 0.125f);
        }
    }

    unsigned long long accp[32];
    #pragma unroll
    for (int i = 0; i < 32; i++) accp[i] = 0ull;
    float m = -1e30f, l = 0.f;

    const int wq0 = warp * 32;
    int wlo = wq0 + 1;
    if (blk == 0 && wlo < WIN) wlo = WIN;
    const int whi = wq0 + 31 + WIN;

    const int ldj  = tid >> 2;
    const int ldsg = (tid & 3) * 16;

    for (int c = 0; c < 8; c++) {
        const int j0 = c * 64;
        {
            const int jj   = j0 + ldj;
            const int kabs = (blk - 1) * WIN + jj;
            if (kabs >= 0) {
                const float* kp = &qkv[(size_t)(b * NSEQ + kabs) * QKVC + DMODEL + h * DH + ldsg];
                const float* vp = kp + DMODEL;
                #pragma unroll
                for (int i = 0; i < 4; i++) {
                    *reinterpret_cast<float4*>(&ks[ldj][ldsg + i * 4]) =
                        *reinterpret_cast<const float4*>(kp + i * 4);
                    *reinterpret_cast<float4*>(&vs[ldj][ldsg + i * 4]) =
                        *reinterpret_cast<const float4*>(vp + i * 4);
                }
            } else {
                #pragma unroll
                for (int i = 0; i < 4; i++) {
                    *reinterpret_cast<float4*>(&ks[ldj][ldsg + i * 4]) = make_float4(0, 0, 0, 0);
                    *reinterpret_cast<float4*>(&vs[ldj][ldsg + i * 4]) = make_float4(0, 0, 0, 0);
                }
            }
        }
        __syncthreads();

        const int jb = max(j0, wlo);
        const int je = min(j0 + 64, whi + 1);
        for (int j = jb; j < je; j += 8) {
            float s[8];
            int   row[8];
            #pragma unroll
            for (int u = 0; u < 8; u++) {
                const int jj = j + u;
                row[u] = (jj - j0) & 63;
                const ulonglong2* kr2 = reinterpret_cast<const ulonglong2*>(ks[row[u]]);
                unsigned long long s0 = 0ull, s1 = 0ull;
                #pragma unroll
                for (int i = 0; i < 16; i++) {
                    ulonglong2 kv = kr2[i];
                    s0 = f2fma(qp[2 * i + 0], kv.x, s0);
                    s1 = f2fma(qp[2 * i + 1], kv.y, s1);
                }
                float2 f = up2(f2add(s0, s1));
                const bool valid = (jj < je) && (jj >= tid + 1) && (jj <= tid + WIN);
                s[u] = valid ? (f.x + f.y) : -1e35f;
            }

            float cmax = s[0];
            #pragma unroll
            for (int u = 1; u < 8; u++) cmax = fmaxf(cmax, s[u]);
            const float mn   = fmaxf(m, cmax);
            const float corr = __expf(m - mn);
            m = mn;

            float p[8], psum = 0.f;
            #pragma unroll
            for (int u = 0; u < 8; u++) { p[u] = __expf(s[u] - mn); psum += p[u]; }
            l = l * corr + psum;

            const unsigned long long cp = pk2(corr, corr);
            #pragma unroll
            for (int i = 0; i < 32; i++) accp[i] = f2mul(accp[i], cp);
            #pragma unroll
            for (int u = 0; u < 8; u++) {
                const ulonglong2* vr2 = reinterpret_cast<const ulonglong2*>(vs[row[u]]);
                const unsigned long long pp = pk2(p[u], p[u]);
                #pragma unroll
                for (int i = 0; i < 16; i++) {
                    ulonglong2 vv = vr2[i];
                    accp[2 * i + 0] = f2fma(pp, vv.x, accp[2 * i + 0]);
                    accp[2 * i + 1] = f2fma(pp, vv.y, accp[2 * i + 1]);
                }
            }
        }
        __syncthreads();
    }

    const float inv = 1.f / l;
    const size_t off = (size_t)(b * NSEQ + blk * WIN + tid) * DMODEL + h * DH;
    #pragma unroll
    for (int i = 0; i < 8; i++) {
        float2 v0 = up2(accp[4 * i + 0]);
        float2 v1 = up2(accp[4 * i + 1]);
        float2 v2 = up2(accp[4 * i + 2]);
        float2 v3 = up2(accp[4 * i + 3]);
        uint4 hq, lq;
        split2(v0.x * inv, v0.y * inv, hq.x, lq.x);
        split2(v1.x * inv, v1.y * inv, hq.y, lq.y);
        split2(v2.x * inv, v2.y * inv, hq.z, lq.z);
        split2(v3.x * inv, v3.y * inv, hq.w, lq.w);
        *reinterpret_cast<uint4*>(oh + off + i * 8) = hq;
        *reinterpret_cast<uint4*>(ol + off + i * 8) = lq;
    }
}

// ---------------------------------------------------------------------------
extern "C" void kernel_launch(void* const* d_in, const int* in_sizes, int n_in,
                              void* d_out, int out_size)
{
    const float* x     = (const float*)d_in[0];   // [4,4096,1024]
    const float* w_qkv = (const float*)d_in[1];   // [1024,3072]
    const float* w_out = (const float*)d_in[2];   // [1024,1024]
    float*       out   = (float*)d_out;           // [4,4096,1024]

    float *qkv;
    __nv_bfloat16 *xh, *xl, *ah, *al, *wqh, *wql, *woh, *wol;
    cudaGetSymbolAddress((void**)&qkv, g_qkv);
    cudaGetSymbolAddress((void**)&xh, g_xh);
    cudaGetSymbolAddress((void**)&xl, g_xl);
    cudaGetSymbolAddress((void**)&ah, g_ah);
    cudaGetSymbolAddress((void**)&al, g_al);
    cudaGetSymbolAddress((void**)&wqh, g_wqh);
    cudaGetSymbolAddress((void**)&wql, g_wql);
    cudaGetSymbolAddress((void**)&woh, g_woh);
    cudaGetSymbolAddress((void**)&wol, g_wol);

    cudaFuncSetAttribute(gemm_mma, cudaFuncAttributeMaxDynamicSharedMemorySize, GSMEM);

    const int nv8 = MTOK * DMODEL / 8;
    split_arr<<<(nv8 + 255) / 256, 256>>>(
        (const float4*)x, (uint4*)xh, (uint4*)xl, nv8);
    split_tr<<<dim3(QKVC / 32, DMODEL / 32), dim3(32, 8)>>>(w_qkv, wqh, wql, DMODEL, QKVC);
    split_tr<<<dim3(DMODEL / 32, DMODEL / 32), dim3(32, 8)>>>(w_out, woh, wol, DMODEL, DMODEL);

    gemm_mma<<<dim3(QKVC / 128, MTOK / 128), 256, GSMEM>>>(
        xh, xl, wqh, wql, qkv, MTOK, QKVC, DMODEL);
    swa_kernel<<<dim3(NSEQ / WIN, BPAR * NH), 256>>>(qkv, ah, al);
    gemm_mma<<<dim3(DMODEL / 128, MTOK / 128), 256, GSMEM>>>(
        ah, al, woh, wol, out, MTOK, DMODEL, DMODEL);
}

// round 5
// speedup vs baseline: 2.4266x; 1.2109x over previous
#include <cuda_runtime.h>
#include <cuda_bf16.h>
#include <math.h>

#define BPAR   4
#define NSEQ   4096
#define DMODEL 1024
#define NH     16
#define DH     64
#define WIN    256
#define MTOK   (BPAR * NSEQ)     /* 16384 */
#define QKVC   (3 * NH * DH)     /* 3072  */

// Scratch (allocation-free rule: __device__ globals)
__device__ __nv_bfloat16 g_xh[(size_t)MTOK * DMODEL];
__device__ __nv_bfloat16 g_xl[(size_t)MTOK * DMODEL];
__device__ __nv_bfloat16 g_qkvh[(size_t)MTOK * QKVC];
__device__ __nv_bfloat16 g_qkvl[(size_t)MTOK * QKVC];
__device__ __nv_bfloat16 g_ah[(size_t)MTOK * DMODEL];
__device__ __nv_bfloat16 g_al[(size_t)MTOK * DMODEL];
__device__ __nv_bfloat16 g_wqh[(size_t)QKVC * DMODEL];
__device__ __nv_bfloat16 g_wql[(size_t)QKVC * DMODEL];
__device__ __nv_bfloat16 g_woh[(size_t)DMODEL * DMODEL];
__device__ __nv_bfloat16 g_wol[(size_t)DMODEL * DMODEL];

// ---------------------------------------------------------------------------
__device__ __forceinline__ unsigned smem_u32(const void* p) {
    unsigned a;
    asm("{ .reg .u64 t; cvta.to.shared.u64 t, %1; cvt.u32.u64 %0, t; }"
        : "=r"(a) : "l"(p));
    return a;
}
// split fp32 pair -> bf16x2 hi word (x in low half) + bf16x2 lo word
__device__ __forceinline__ void split2(float x, float y, unsigned& h, unsigned& l) {
    unsigned xb = __float_as_uint(x) & 0xFFFF0000u;
    unsigned yb = __float_as_uint(y) & 0xFFFF0000u;
    h = __byte_perm(xb, yb, 0x7632);
    float rx = x - __uint_as_float(xb);
    float ry = y - __uint_as_float(yb);
    __nv_bfloat162 t = __floats2bfloat162_rn(rx, ry);
    l = *reinterpret_cast<unsigned*>(&t);
}
__device__ __forceinline__ void mma16816(
    float& c0, float& c1, float& c2, float& c3,
    unsigned a0, unsigned a1, unsigned a2, unsigned a3,
    unsigned b0, unsigned b1) {
    asm volatile(
        "mma.sync.aligned.m16n8k16.row.col.f32.bf16.bf16.f32 "
        "{%0,%1,%2,%3},{%4,%5,%6,%7},{%8,%9},{%0,%1,%2,%3};"
        : "+f"(c0), "+f"(c1), "+f"(c2), "+f"(c3)
        : "r"(a0), "r"(a1), "r"(a2), "r"(a3), "r"(b0), "r"(b1));
}
__device__ __forceinline__ void cp16(unsigned saddr, const void* g) {
    asm volatile("cp.async.cg.shared.global [%0], [%1], 16;"
                 :: "r"(saddr), "l"(g) : "memory");
}
#define LDSM4(r, a)                                                           \
    asm volatile("ldmatrix.sync.aligned.m8n8.x4.shared.b16 {%0,%1,%2,%3},[%4];" \
                 : "=r"((r)[0]), "=r"((r)[1]), "=r"((r)[2]), "=r"((r)[3])     \
                 : "r"(a))
#define LDSM4T(r, a)                                                          \
    asm volatile("ldmatrix.sync.aligned.m8n8.x4.trans.shared.b16 {%0,%1,%2,%3},[%4];" \
                 : "=r"((r)[0]), "=r"((r)[1]), "=r"((r)[2]), "=r"((r)[3])     \
                 : "r"(a))

// ---------------------------------------------------------------------------
// prepass: elementwise fp32 -> bf16 hi/lo
// ---------------------------------------------------------------------------
__global__ __launch_bounds__(256) void split_arr(
    const float4* __restrict__ src, uint4* __restrict__ hi,
    uint4* __restrict__ lo, int nvec8)
{
    int i = blockIdx.x * 256 + threadIdx.x;
    if (i >= nvec8) return;
    float4 f0 = src[2 * i], f1 = src[2 * i + 1];
    uint4 h, l;
    split2(f0.x, f0.y, h.x, l.x); split2(f0.z, f0.w, h.y, l.y);
    split2(f1.x, f1.y, h.z, l.z); split2(f1.z, f1.w, h.w, l.w);
    hi[i] = h; lo[i] = l;
}
// prepass: transpose+split, src [K][N] fp32 -> hi/lo [N][K] bf16.
// columns n < nscale get scaled by 0.125 (exact pow2; folds q-scale into W).
__global__ void split_tr(const float* __restrict__ src,
                         __nv_bfloat16* __restrict__ hi,
                         __nv_bfloat16* __restrict__ lo, int K, int N, int nscale)
{
    __shared__ float tile[32][33];
    const int n0 = blockIdx.x * 32, k0 = blockIdx.y * 32;
    const int tx = threadIdx.x, ty = threadIdx.y;
    #pragma unroll
    for (int j = ty; j < 32; j += 8)
        tile[j][tx] = src[(size_t)(k0 + j) * N + n0 + tx];
    __syncthreads();
    #pragma unroll
    for (int j = ty; j < 32; j += 8) {
        float sc = (n0 + j < nscale) ? 0.125f : 1.0f;
        float v = tile[tx][j] * sc;
        unsigned vb = __float_as_uint(v) & 0xFFFF0000u;
        size_t o = (size_t)(n0 + j) * K + k0 + tx;
        unsigned short hs = (unsigned short)(vb >> 16);
        hi[o] = *reinterpret_cast<__nv_bfloat16*>(&hs);
        lo[o] = __float2bfloat16_rn(v - __uint_as_float(vb));
    }
}

// ---------------------------------------------------------------------------
// split-bf16 HMMA GEMM, double-buffered cp.async.
// A hi/lo [M][K], B hi/lo [N][K] bf16. Out: fp32 Cf OR bf16 hi/lo Ch/Cl.
// ---------------------------------------------------------------------------
#define TILE_B 10240
#define STG_B  40960
#define GSMEM  (2 * STG_B)

__device__ __forceinline__ void gload(
    unsigned sb, int st, int tid,
    const __nv_bfloat16* b0, const __nv_bfloat16* b1,
    const __nv_bfloat16* b2, const __nv_bfloat16* b3, int K, int k0)
{
    const __nv_bfloat16* base[4] = {b0, b1, b2, b3};
    const int rlo = tid >> 2;
    const int pel = (tid & 3) << 3;
    const int pby = (tid & 3) << 4;
    #pragma unroll
    for (int i = 0; i < 8; i++) {
        const int tl  = i >> 1;
        const int row = ((i & 1) << 6) + rlo;
        cp16(sb + st * STG_B + tl * TILE_B + row * 80 + pby,
             base[tl] + (size_t)row * K + k0 + pel);
    }
    asm volatile("cp.async.commit_group;" ::: "memory");
}

__global__ __launch_bounds__(256, 2) void gemm_mma(
    const __nv_bfloat16* __restrict__ Ah, const __nv_bfloat16* __restrict__ Al,
    const __nv_bfloat16* __restrict__ Bh, const __nv_bfloat16* __restrict__ Bl,
    float* __restrict__ Cf, __nv_bfloat16* __restrict__ Ch,
    __nv_bfloat16* __restrict__ Cl, int M, int N, int K)
{
    extern __shared__ char dsm[];
    const unsigned sb = smem_u32(dsm);

    const int tid = threadIdx.x;
    const int wid = tid >> 5, lid = tid & 31;
    const int g = lid >> 2, t = lid & 3;
    const int wm = (wid >> 2) * 64;
    const int wn = (wid & 3) * 32;
    const int m0 = blockIdx.y * 128, n0 = blockIdx.x * 128;

    const __nv_bfloat16* a_h = Ah + (size_t)m0 * K;
    const __nv_bfloat16* a_l = Al + (size_t)m0 * K;
    const __nv_bfloat16* b_h = Bh + (size_t)n0 * K;
    const __nv_bfloat16* b_l = Bl + (size_t)n0 * K;

    float acc[4][4][4];
    #pragma unroll
    for (int i = 0; i < 4; i++)
        #pragma unroll
        for (int j = 0; j < 4; j++)
            #pragma unroll
            for (int e = 0; e < 4; e++) acc[i][j][e] = 0.f;

    const int nk = K >> 5;
    gload(sb, 0, tid, a_h, a_l, b_h, b_l, K, 0);

    for (int kc = 0; kc < nk; kc++) {
        if (kc + 1 < nk) {
            gload(sb, (kc + 1) & 1, tid, a_h, a_l, b_h, b_l, K, (kc + 1) << 5);
            asm volatile("cp.async.wait_group 1;" ::: "memory");
        } else {
            asm volatile("cp.async.wait_group 0;" ::: "memory");
        }
        __syncthreads();

        const int st = kc & 1;
        const unsigned* pAh = reinterpret_cast<const unsigned*>(dsm + st * STG_B);
        const unsigned* pAl = pAh + 2560;
        const unsigned* pBh = pAh + 5120;
        const unsigned* pBl = pAh + 7680;

        #pragma unroll
        for (int s = 0; s < 2; s++) {
            const int w = s * 8 + t;
            unsigned ah[4][4], al[4][4];
            #pragma unroll
            for (int tm = 0; tm < 4; tm++) {
                const int r0 = (wm + tm * 16 + g) * 20;
                const int r1 = r0 + 8 * 20;
                ah[tm][0] = pAh[r0 + w];     ah[tm][1] = pAh[r1 + w];
                ah[tm][2] = pAh[r0 + w + 4]; ah[tm][3] = pAh[r1 + w + 4];
                al[tm][0] = pAl[r0 + w];     al[tm][1] = pAl[r1 + w];
                al[tm][2] = pAl[r0 + w + 4]; al[tm][3] = pAl[r1 + w + 4];
            }
            #pragma unroll
            for (int tn = 0; tn < 4; tn++) {
                const int nr = (wn + tn * 8 + g) * 20;
                const unsigned bh0 = pBh[nr + w], bh1 = pBh[nr + w + 4];
                const unsigned bl0 = pBl[nr + w], bl1 = pBl[nr + w + 4];
                #pragma unroll
                for (int tm = 0; tm < 4; tm++) {
                    float* c = acc[tm][tn];
                    mma16816(c[0], c[1], c[2], c[3],
                             ah[tm][0], ah[tm][1], ah[tm][2], ah[tm][3], bh0, bh1);
                    mma16816(c[0], c[1], c[2], c[3],
                             ah[tm][0], ah[tm][1], ah[tm][2], ah[tm][3], bl0, bl1);
                    mma16816(c[0], c[1], c[2], c[3],
                             al[tm][0], al[tm][1], al[tm][2], al[tm][3], bh0, bh1);
                }
            }
        }
        __syncthreads();
    }

    #pragma unroll
    for (int tm = 0; tm < 4; tm++) {
        #pragma unroll
        for (int tn = 0; tn < 4; tn++) {
            float* c = acc[tm][tn];
            size_t r0 = (size_t)(m0 + wm + tm * 16 + g) * N + n0 + wn + tn * 8 + 2 * t;
            if (Cf) {
                *reinterpret_cast<float2*>(Cf + r0)             = make_float2(c[0], c[1]);
                *reinterpret_cast<float2*>(Cf + r0 + 8 * (size_t)N) = make_float2(c[2], c[3]);
            } else {
                unsigned hw, lw;
                split2(c[0], c[1], hw, lw);
                *reinterpret_cast<unsigned*>(Ch + r0) = hw;
                *reinterpret_cast<unsigned*>(Cl + r0) = lw;
                split2(c[2], c[3], hw, lw);
                *reinterpret_cast<unsigned*>(Ch + r0 + 8 * (size_t)N) = hw;
                *reinterpret_cast<unsigned*>(Cl + r0 + 8 * (size_t)N) = lw;
            }
        }
    }
}

// ---------------------------------------------------------------------------
// HMMA sliding-window attention. grid = (NSEQ/128 = 32, B*H = 64), 256 thr.
// Q (128xDH, split) vs 3 key chunks of 128. Tile-skip gives exactly 34 score
// tiles & 17 PV k-blocks per warp. Row pad 144B -> conflict-free ldmatrix.
// ---------------------------------------------------------------------------
#define RB    144
#define QPL   18432              /* one 128-row plane */
#define ASMEM (10 * QPL)         /* Q(2) + K(2 stages x2) + V(2x2) = 184320 */

__global__ __launch_bounds__(256, 1) void swa_mma(
    const __nv_bfloat16* __restrict__ qkvh,
    const __nv_bfloat16* __restrict__ qkvl,
    __nv_bfloat16* __restrict__ oh, __nv_bfloat16* __restrict__ ol)
{
    extern __shared__ char sm[];
    const unsigned sb = smem_u32(sm);
    const int blkq = blockIdx.x;
    const int bh = blockIdx.y, b = bh >> 4, hh = bh & 15;
    const int tid = threadIdx.x, w = tid >> 5, lid = tid & 31;
    const int g = lid >> 2, t = lid & 3;
    const int q0 = blkq * 128;
    const size_t tokb = (size_t)b * NSEQ;

    const unsigned sQ = sb;                  // [hi,lo] planes
    const unsigned sK = sb + 2 * QPL;        // [stage][hi,lo]
    const unsigned sV = sb + 6 * QPL;

    // stage Q (hi+lo)
    {
        int r = tid >> 1, hl = tid & 1;
        const __nv_bfloat16* src =
            (hl ? qkvl : qkvh) + (tokb + q0 + r) * QKVC + hh * DH;
        unsigned dst = sQ + hl * QPL + r * RB;
        #pragma unroll
        for (int s = 0; s < 8; s++) cp16(dst + s * 16, src + s * 8);
    }
    asm volatile("cp.async.commit_group;" ::: "memory");

    const int cstart = (q0 >= 256) ? 0 : (q0 >= 128 ? 1 : 2);

    // chunk K/V load: threads 0-127 -> K rows, 128-255 -> V rows
    auto ldkv = [&](int c, int st) {
        const int kb = q0 - 256 + c * 128;
        const int r = tid & 127;
        const int isv = tid >> 7;
        const size_t row = tokb + kb + r;
        const int off = (isv ? 2 * DMODEL : DMODEL) + hh * DH;
        const __nv_bfloat16* sh = qkvh + row * QKVC + off;
        const __nv_bfloat16* sl = qkvl + row * QKVC + off;
        unsigned base = (isv ? sV : sK) + st * 2 * QPL + r * RB;
        #pragma unroll
        for (int s = 0; s < 8; s++) {
            cp16(base + s * 16, sh + s * 8);
            cp16(base + QPL + s * 16, sl + s * 8);
        }
        asm volatile("cp.async.commit_group;" ::: "memory");
    };

    ldkv(cstart, 0);
    asm volatile("cp.async.wait_group 0;" ::: "memory");
    __syncthreads();

    // Q fragments (held in regs for whole kernel)
    unsigned qh[4][4], ql[4][4];
    {
        unsigned ab = sQ + (w * 16 + (lid & 15)) * RB + (lid >> 4) * 16;
        #pragma unroll
        for (int ks = 0; ks < 4; ks++) {
            LDSM4(qh[ks], ab + ks * 32);
            LDSM4(ql[ks], ab + QPL + ks * 32);
        }
    }

    float O[8][4];
    #pragma unroll
    for (int i = 0; i < 8; i++)
        #pragma unroll
        for (int e = 0; e < 4; e++) O[i][e] = 0.f;
    float m0 = -1e30f, m1 = -1e30f, l0 = 0.f, l1 = 0.f;
    const int qi0 = q0 + w * 16 + g, qi1 = qi0 + 8;

    const unsigned klane = (lid & 7) * RB + (lid >> 3) * 16;
    const unsigned vlane = (lid & 15) * RB + (lid >> 4) * 16;

    for (int c = cstart; c <= 2; ++c) {
        const int st = (c - cstart) & 1;
        if (c < 2) ldkv(c + 1, st ^ 1);

        const int kb = q0 - 256 + c * 128;
        const int tnlo = (c == 0) ? 2 * w : 0;
        const int tnhi = (c == 2) ? 2 * w + 1 : 15;
        const unsigned kbase = sK + st * 2 * QPL + klane;
        const unsigned vbase = sV + st * 2 * QPL + vlane;

        // ---- scores ----
        float S[16][4];
        #pragma unroll
        for (int tn = 0; tn < 16; tn++) {
            if (tn < tnlo || tn > tnhi) continue;
            S[tn][0] = S[tn][1] = S[tn][2] = S[tn][3] = 0.f;
            #pragma unroll
            for (int sp = 0; sp < 2; sp++) {
                unsigned kh[4], kl[4];
                unsigned ka = kbase + tn * (8 * RB) + sp * 64;
                LDSM4(kh, ka);
                LDSM4(kl, ka + QPL);
                float* c4 = S[tn];
                mma16816(c4[0], c4[1], c4[2], c4[3],
                         qh[2*sp][0], qh[2*sp][1], qh[2*sp][2], qh[2*sp][3], kh[0], kh[1]);
                mma16816(c4[0], c4[1], c4[2], c4[3],
                         qh[2*sp][0], qh[2*sp][1], qh[2*sp][2], qh[2*sp][3], kl[0], kl[1]);
                mma16816(c4[0], c4[1], c4[2], c4[3],
                         ql[2*sp][0], ql[2*sp][1], ql[2*sp][2], ql[2*sp][3], kh[0], kh[1]);
                mma16816(c4[0], c4[1], c4[2], c4[3],
                         qh[2*sp+1][0], qh[2*sp+1][1], qh[2*sp+1][2], qh[2*sp+1][3], kh[2], kh[3]);
                mma16816(c4[0], c4[1], c4[2], c4[3],
                         qh[2*sp+1][0], qh[2*sp+1][1], qh[2*sp+1][2], qh[2*sp+1][3], kl[2], kl[3]);
                mma16816(c4[0], c4[1], c4[2], c4[3],
                         ql[2*sp+1][0], ql[2*sp+1][1], ql[2*sp+1][2], ql[2*sp+1][3], kh[2], kh[3]);
            }
        }

        // ---- mask + online softmax ----
        float cm0 = -1e30f, cm1 = -1e30f;
        #pragma unroll
        for (int tn = 0; tn < 16; tn++) {
            if (tn < tnlo || tn > tnhi) continue;
            const int k0c = kb + tn * 8 + 2 * t;
            if (c == 0) {   // lower bound: kabs >= qi-255
                if (k0c     < qi0 - 255) S[tn][0] = -1e30f;
                if (k0c + 1 < qi0 - 255) S[tn][1] = -1e30f;
                if (k0c     < qi1 - 255) S[tn][2] = -1e30f;
                if (k0c + 1 < qi1 - 255) S[tn][3] = -1e30f;
            } else if (c == 2) {  // upper bound: kabs <= qi
                if (k0c     > qi0) S[tn][0] = -1e30f;
                if (k0c + 1 > qi0) S[tn][1] = -1e30f;
                if (k0c     > qi1) S[tn][2] = -1e30f;
                if (k0c + 1 > qi1) S[tn][3] = -1e30f;
            }
            cm0 = fmaxf(cm0, fmaxf(S[tn][0], S[tn][1]));
            cm1 = fmaxf(cm1, fmaxf(S[tn][2], S[tn][3]));
        }
        cm0 = fmaxf(cm0, __shfl_xor_sync(0xFFFFFFFFu, cm0, 1));
        cm0 = fmaxf(cm0, __shfl_xor_sync(0xFFFFFFFFu, cm0, 2));
        cm1 = fmaxf(cm1, __shfl_xor_sync(0xFFFFFFFFu, cm1, 1));
        cm1 = fmaxf(cm1, __shfl_xor_sync(0xFFFFFFFFu, cm1, 2));
        const float mn0 = fmaxf(m0, cm0), mn1 = fmaxf(m1, cm1);
        const float corr0 = __expf(m0 - mn0), corr1 = __expf(m1 - mn1);
        m0 = mn0; m1 = mn1;

        float ls0 = 0.f, ls1 = 0.f;
        #pragma unroll
        for (int tn = 0; tn < 16; tn++) {
            if (tn < tnlo || tn > tnhi) continue;
            S[tn][0] = __expf(S[tn][0] - m0);
            S[tn][1] = __expf(S[tn][1] - m0);
            S[tn][2] = __expf(S[tn][2] - m1);
            S[tn][3] = __expf(S[tn][3] - m1);
            ls0 += S[tn][0] + S[tn][1];
            ls1 += S[tn][2] + S[tn][3];
        }
        l0 = l0 * corr0 + ls0;
        l1 = l1 * corr1 + ls1;
        #pragma unroll
        for (int i = 0; i < 8; i++) {
            O[i][0] *= corr0; O[i][1] *= corr0;
            O[i][2] *= corr1; O[i][3] *= corr1;
        }

        // ---- PV ----
        const int jlo = (c == 0) ? w : 0;
        const int jhi = (c == 2) ? w : 7;
        #pragma unroll
        for (int j = 0; j < 8; j++) {
            if (j < jlo || j > jhi) continue;
            unsigned ph[4], pl[4];
            split2(S[2*j][0],   S[2*j][1],   ph[0], pl[0]);
            split2(S[2*j][2],   S[2*j][3],   ph[1], pl[1]);
            split2(S[2*j+1][0], S[2*j+1][1], ph[2], pl[2]);
            split2(S[2*j+1][2], S[2*j+1][3], ph[3], pl[3]);
            #pragma unroll
            for (int tp = 0; tp < 4; tp++) {
                unsigned vh[4], vl[4];
                unsigned va = vbase + j * (16 * RB) + tp * 32;
                LDSM4T(vh, va);
                LDSM4T(vl, va + QPL);
                float* cA = O[2 * tp];
                float* cB = O[2 * tp + 1];
                mma16816(cA[0], cA[1], cA[2], cA[3],
                         ph[0], ph[1], ph[2], ph[3], vh[0], vh[1]);
                mma16816(cA[0], cA[1], cA[2], cA[3],
                         ph[0], ph[1], ph[2], ph[3], vl[0], vl[1]);
                mma16816(cA[0], cA[1], cA[2], cA[3],
                         pl[0], pl[1], pl[2], pl[3], vh[0], vh[1]);
                mma16816(cB[0], cB[1], cB[2], cB[3],
                         ph[0], ph[1], ph[2], ph[3], vh[2], vh[3]);
                mma16816(cB[0], cB[1], cB[2], cB[3],
                         ph[0], ph[1], ph[2], ph[3], vl[2], vl[3]);
                mma16816(cB[0], cB[1], cB[2], cB[3],
                         pl[0], pl[1], pl[2], pl[3], vh[2], vh[3]);
            }
        }

        if (c < 2) asm volatile("cp.async.wait_group 0;" ::: "memory");
        __syncthreads();
    }

    // ---- epilogue ----
    l0 += __shfl_xor_sync(0xFFFFFFFFu, l0, 1);
    l0 += __shfl_xor_sync(0xFFFFFFFFu, l0, 2);
    l1 += __shfl_xor_sync(0xFFFFFFFFu, l1, 1);
    l1 += __shfl_xor_sync(0xFFFFFFFFu, l1, 2);
    const float i0 = 1.f / l0, i1 = 1.f / l1;
    const size_t t0 = (tokb + q0 + w * 16 + g) * DMODEL + hh * DH;
    const size_t t1 = t0 + 8 * DMODEL;
    #pragma unroll
    for (int tp = 0; tp < 8; tp++) {
        const int col = tp * 8 + 2 * t;
        unsigned hw, lw;
        split2(O[tp][0] * i0, O[tp][1] * i0, hw, lw);
        *reinterpret_cast<unsigned*>(oh + t0 + col) = hw;
        *reinterpret_cast<unsigned*>(ol + t0 + col) = lw;
        split2(O[tp][2] * i1, O[tp][3] * i1, hw, lw);
        *reinterpret_cast<unsigned*>(oh + t1 + col) = hw;
        *reinterpret_cast<unsigned*>(ol + t1 + col) = lw;
    }
}

// ---------------------------------------------------------------------------
extern "C" void kernel_launch(void* const* d_in, const int* in_sizes, int n_in,
                              void* d_out, int out_size)
{
    const float* x     = (const float*)d_in[0];
    const float* w_qkv = (const float*)d_in[1];
    const float* w_out = (const float*)d_in[2];
    float*       out   = (float*)d_out;

    __nv_bfloat16 *xh, *xl, *qkvh, *qkvl, *ah, *al, *wqh, *wql, *woh, *wol;
    cudaGetSymbolAddress((void**)&xh, g_xh);
    cudaGetSymbolAddress((void**)&xl, g_xl);
    cudaGetSymbolAddress((void**)&qkvh, g_qkvh);
    cudaGetSymbolAddress((void**)&qkvl, g_qkvl);
    cudaGetSymbolAddress((void**)&ah, g_ah);
    cudaGetSymbolAddress((void**)&al, g_al);
    cudaGetSymbolAddress((void**)&wqh, g_wqh);
    cudaGetSymbolAddress((void**)&wql, g_wql);
    cudaGetSymbolAddress((void**)&woh, g_woh);
    cudaGetSymbolAddress((void**)&wol, g_wol);

    cudaFuncSetAttribute(gemm_mma, cudaFuncAttributeMaxDynamicSharedMemorySize, GSMEM);
    cudaFuncSetAttribute(swa_mma, cudaFuncAttributeMaxDynamicSharedMemorySize, ASMEM);

    const int nv8 = MTOK * DMODEL / 8;
    split_arr<<<(nv8 + 255) / 256, 256>>>((const float4*)x, (uint4*)xh, (uint4*)xl, nv8);
    // fold q-scale (DH^-1/2 = 1/8, exact pow2) into the q-columns of w_qkv
    split_tr<<<dim3(QKVC / 32, DMODEL / 32), dim3(32, 8)>>>(
        w_qkv, wqh, wql, DMODEL, QKVC, DMODEL);
    split_tr<<<dim3(DMODEL / 32, DMODEL / 32), dim3(32, 8)>>>(
        w_out, woh, wol, DMODEL, DMODEL, 0);

    gemm_mma<<<dim3(QKVC / 128, MTOK / 128), 256, GSMEM>>>(
        xh, xl, wqh, wql, nullptr, qkvh, qkvl, MTOK, QKVC, DMODEL);
    swa_mma<<<dim3(NSEQ / 128, BPAR * NH), 256, ASMEM>>>(qkvh, qkvl, ah, al);
    gemm_mma<<<dim3(DMODEL / 128, MTOK / 128), 256, GSMEM>>>(
        ah, al, woh, wol, out, nullptr, nullptr, MTOK, DMODEL, DMODEL);
}